// round 13
// baseline (speedup 1.0000x reference)
#include <cuda_runtime.h>
#include <cuda_bf16.h>
#include <cstdint>
#include <math.h>

#define BATCH    4
#define N_TOK    16384
#define D        192
#define DFF      768
#define HEADS    6
#define DH       32
#define M_CL     64
#define KC       (N_TOK / M_CL)
#define BN_ROWS  (BATCH * N_TOK)     // 65536
#define GRID_W   128

typedef __nv_bfloat16 bf16;

// ---------------- scratch ----------------------------------------------------
__device__ bf16  g_xn  [BN_ROWS * D];
__device__ bf16  g_qkv [BN_ROWS * 3 * D];
__device__ bf16  g_o   [BN_ROWS * D];
__device__ bf16  g_h   [BN_ROWS * DFF];
__device__ bf16  g_wqkv[2 * D * 3 * D];     // [K][N] bf16
__device__ bf16  g_wprj[2 * D * D];
__device__ bf16  g_wfc1[2 * D * DFF];
__device__ bf16  g_wfc2[2 * DFF * D];
__device__ int   g_ord[BN_ROWS];
__device__ int   g_inv[BN_ROWS];

// ---------------- helpers ----------------------------------------------------
__device__ __forceinline__ uint32_t smem_u32(const void* p) {
    uint32_t a;
    asm("{ .reg .u64 t; cvta.to.shared.u64 t, %1; cvt.u32.u64 %0, t; }"
        : "=r"(a) : "l"(p));
    return a;
}
__device__ __forceinline__ void cpasync16(uint32_t saddr, const void* g) {
    asm volatile("cp.async.cg.shared.global [%0], [%1], 16;"
                 :: "r"(saddr), "l"(g) : "memory");
}
__device__ __forceinline__ void ldsm_x4(uint32_t* r, uint32_t addr) {
    asm volatile("ldmatrix.sync.aligned.m8n8.x4.shared.b16 {%0,%1,%2,%3}, [%4];"
                 : "=r"(r[0]), "=r"(r[1]), "=r"(r[2]), "=r"(r[3]) : "r"(addr));
}
__device__ __forceinline__ void ldsm_x4t(uint32_t* r, uint32_t addr) {
    asm volatile("ldmatrix.sync.aligned.m8n8.x4.trans.shared.b16 {%0,%1,%2,%3}, [%4];"
                 : "=r"(r[0]), "=r"(r[1]), "=r"(r[2]), "=r"(r[3]) : "r"(addr));
}
__device__ __forceinline__ void mma16816(float* c, const uint32_t* a,
                                         const uint32_t* b) {
    asm volatile(
        "mma.sync.aligned.m16n8k16.row.col.f32.bf16.bf16.f32 "
        "{%0,%1,%2,%3}, {%4,%5,%6,%7}, {%8,%9}, {%0,%1,%2,%3};"
        : "+f"(c[0]), "+f"(c[1]), "+f"(c[2]), "+f"(c[3])
        : "r"(a[0]), "r"(a[1]), "r"(a[2]), "r"(a[3]), "r"(b[0]), "r"(b[1]));
}
__device__ __forceinline__ uint32_t packbf2(float lo, float hi) {
    __nv_bfloat162 pk;
    pk.x = __float2bfloat16(lo);
    pk.y = __float2bfloat16(hi);
    return *(uint32_t*)&pk;
}

// ---------------- fused prep: weights->bf16 + curve order -------------------
#define SZ_QKV (2 * D * 3 * D)
#define SZ_PRJ (2 * D * D)
#define SZ_FC1 (2 * D * DFF)
#define SZ_FC2 (2 * DFF * D)
__global__ void prep_kernel(const float* __restrict__ wq, const float* __restrict__ wp,
                            const float* __restrict__ w1, const float* __restrict__ w2,
                            const float* __restrict__ pos) {
    int i = blockIdx.x * blockDim.x + threadIdx.x;
    if (i < SZ_QKV) g_wqkv[i] = __float2bfloat16(wq[i]);
    if (i < SZ_PRJ) g_wprj[i] = __float2bfloat16(wp[i]);
    if (i < SZ_FC1) g_wfc1[i] = __float2bfloat16(w1[i]);
    if (i < SZ_FC2) g_wfc2[i] = __float2bfloat16(w2[i]);
    if (i < BN_ROWS) {
        int b = i / N_TOK;
        int ix = (int)floorf(pos[(size_t)i * 2 + 0]);
        int iy = (int)floorf(pos[(size_t)i * 2 + 1]);
        int key = iy * GRID_W + ((iy & 1) ? (GRID_W - 1 - ix) : ix);
        int rank = b * N_TOK + key;
        g_inv[i]    = rank;
        g_ord[rank] = i;
    }
}

// ---------------- layernorm --------------------------------------------------
__global__ void ln_kernel(const float* __restrict__ x,
                          const float* __restrict__ gamma,
                          const float* __restrict__ beta,
                          bf16* __restrict__ out) {
    int warp = (blockIdx.x * blockDim.x + threadIdx.x) >> 5;
    int lane = threadIdx.x & 31;
    if (warp >= BN_ROWS) return;
    const float* xr = x + (size_t)warp * D;
    float v[6];
    float s = 0.f, s2 = 0.f;
#pragma unroll
    for (int j = 0; j < 6; j++) {
        v[j] = xr[lane + 32 * j];
        s += v[j]; s2 += v[j] * v[j];
    }
#pragma unroll
    for (int o = 16; o; o >>= 1) {
        s  += __shfl_xor_sync(0xffffffffu, s,  o);
        s2 += __shfl_xor_sync(0xffffffffu, s2, o);
    }
    float mean = s * (1.f / D);
    float var  = s2 * (1.f / D) - mean * mean;
    float rstd = rsqrtf(var + 1e-5f);
    bf16* orow = out + (size_t)warp * D;
#pragma unroll
    for (int j = 0; j < 6; j++) {
        int c = lane + 32 * j;
        orow[c] = __float2bfloat16((v[j] - mean) * rstd * gamma[c] + beta[c]);
    }
}

__device__ __forceinline__ float gelu_tanh(float v) {
    float c = v + 0.044715f * v * v * v;
    return 0.5f * v * (1.f + tanhf(0.7978845608028654f * c));
}

// ---------------- raw mma.sync GEMM (QKV / PRJ / FC2) ------------------------
#define BMm   128
#define BNm   64
#define BKm   64
#define LDAS  72
#define LDBS  72
#define AST   (BMm * LDAS)
#define BST   (BKm * LDBS)
#define STAGE (AST + BST)
#define SMEMB (2 * STAGE * 2)

template <int ACT, bool SCATTER, bool RES, bool OUTBF>
__global__ __launch_bounds__(128) void gemm_mma(
        const bf16*  __restrict__ A,
        const bf16*  __restrict__ W,
        const float* __restrict__ bias,
        const float* __restrict__ res,
        const int*   __restrict__ omap,
        void* __restrict__ Cout,
        int K, int N) {
    extern __shared__ __align__(16) bf16 sm[];
    uint32_t sbase = smem_u32(sm);

    int tid   = threadIdx.x;
    int wid   = tid >> 5;
    int lane  = tid & 31;
    int warpM = wid >> 1;
    int warpN = wid & 1;
    int mbase = blockIdx.y * BMm;
    int nbase = blockIdx.x * BNm;

    float c[4][4][4];
#pragma unroll
    for (int mi = 0; mi < 4; mi++)
#pragma unroll
        for (int ni = 0; ni < 4; ni++)
#pragma unroll
            for (int e = 0; e < 4; e++) c[mi][ni][e] = 0.f;

    int aRow  = warpM * 64 + (lane & 15);
    int aKad  = (lane >> 4) << 3;
    int bKad  = ((lane >> 3) & 1) * 8 + (lane & 7);
    int bNad  = warpN * 32 + ((lane >> 4) << 3);

    const int nch = K / BKm;

    auto load_stage = [&](int st, int k0) {
        uint32_t sA = sbase + (uint32_t)(st * STAGE) * 2;
        uint32_t sB = sA + (uint32_t)AST * 2;
#pragma unroll
        for (int p = 0; p < 8; p++) {
            int idx = tid + p * 128;
            int r = idx >> 3, cc = (idx & 7) * 8;
            cpasync16(sA + (uint32_t)(r * LDAS + cc) * 2,
                      &A[(size_t)(mbase + r) * K + k0 + cc]);
        }
#pragma unroll
        for (int p = 0; p < 4; p++) {
            int idx = tid + p * 128;
            int r = idx >> 3, cc = (idx & 7) * 8;
            cpasync16(sB + (uint32_t)(r * LDBS + cc) * 2,
                      &W[(size_t)(k0 + r) * N + nbase + cc]);
        }
        asm volatile("cp.async.commit_group;" ::: "memory");
    };

    load_stage(0, 0);
    for (int kc = 0; kc < nch; kc++) {
        if (kc + 1 < nch) load_stage((kc + 1) & 1, (kc + 1) * BKm);
        if (kc + 1 < nch)
            asm volatile("cp.async.wait_group 1;" ::: "memory");
        else
            asm volatile("cp.async.wait_group 0;" ::: "memory");
        __syncthreads();

        uint32_t sA = sbase + (uint32_t)((kc & 1) * STAGE) * 2;
        uint32_t sB = sA + (uint32_t)AST * 2;
#pragma unroll
        for (int kk = 0; kk < BKm; kk += 16) {
            uint32_t af[4][4], bfr[2][4];
#pragma unroll
            for (int mi = 0; mi < 4; mi++)
                ldsm_x4(af[mi],
                    sA + (uint32_t)((aRow + mi * 16) * LDAS + kk + aKad) * 2);
#pragma unroll
            for (int nh = 0; nh < 2; nh++)
                ldsm_x4t(bfr[nh],
                    sB + (uint32_t)((kk + bKad) * LDBS + bNad + nh * 16) * 2);
#pragma unroll
            for (int mi = 0; mi < 4; mi++)
#pragma unroll
                for (int ni = 0; ni < 4; ni++)
                    mma16816(c[mi][ni], af[mi], &bfr[ni >> 1][(ni & 1) * 2]);
        }
        __syncthreads();
    }

    int grp = lane >> 2;
    int qid = lane & 3;
#pragma unroll
    for (int mi = 0; mi < 4; mi++) {
#pragma unroll
        for (int ni = 0; ni < 4; ni++) {
            int col = nbase + warpN * 32 + ni * 8 + qid * 2;
            float b0 = bias[col], b1 = bias[col + 1];
#pragma unroll
            for (int half = 0; half < 2; half++) {
                int row = mbase + warpM * 64 + mi * 16 + grp + half * 8;
                int orow = SCATTER ? omap[row] : row;
                float v0 = c[mi][ni][half * 2 + 0] + b0;
                float v1 = c[mi][ni][half * 2 + 1] + b1;
                if (ACT == 1) { v0 = gelu_tanh(v0); v1 = gelu_tanh(v1); }
                if (RES) {
                    const float2 r2 = *(const float2*)&res[(size_t)orow * N + col];
                    v0 += r2.x; v1 += r2.y;
                }
                if (OUTBF) {
                    *(uint32_t*)&((bf16*)Cout)[(size_t)orow * N + col] = packbf2(v0, v1);
                } else {
                    float2 o2; o2.x = v0; o2.y = v1;
                    *(float2*)&((float*)Cout)[(size_t)orow * N + col] = o2;
                }
            }
        }
    }
}

// ---------------- wide-tile GEMM for FC1: BM=128, BN=128, 4 warps -----------
// Warp tile 64x64: 32 MMA per 8 LDSM per kk-step. gelu + bf16 out.
#define WLDA 72
#define WLDB 136
#define WAST (128 * WLDA)          // 9216 elem
#define WBST (64 * WLDB)           // 8704 elem
#define WSTG (WAST + WBST)         // 17920 elem
#define SMEMW (2 * WSTG * 2)       // 71680 B

__global__ __launch_bounds__(128, 2) void gemm_w128(
        const bf16*  __restrict__ A,
        const bf16*  __restrict__ W,
        const float* __restrict__ bias,
        bf16* __restrict__ Cout,
        int K, int N) {
    extern __shared__ __align__(16) bf16 sm[];
    uint32_t sbase = smem_u32(sm);

    int tid   = threadIdx.x;
    int wid   = tid >> 5;
    int lane  = tid & 31;
    int warpM = wid >> 1;          // 0,1
    int warpN = wid & 1;           // 0,1
    int mbase = blockIdx.y * 128;
    int nbase = blockIdx.x * 128;

    float c[4][8][4];
#pragma unroll
    for (int mi = 0; mi < 4; mi++)
#pragma unroll
        for (int ni = 0; ni < 8; ni++)
#pragma unroll
            for (int e = 0; e < 4; e++) c[mi][ni][e] = 0.f;

    int aRow = warpM * 64 + (lane & 15);
    int aKad = (lane >> 4) << 3;
    int bKad = ((lane >> 3) & 1) * 8 + (lane & 7);
    int bNad = warpN * 64 + ((lane >> 4) << 3);

    const int nch = K / 64;

    auto load_stage = [&](int st, int k0) {
        uint32_t sA = sbase + (uint32_t)(st * WSTG) * 2;
        uint32_t sB = sA + (uint32_t)WAST * 2;
#pragma unroll
        for (int p = 0; p < 8; p++) {          // A: 128x64 = 1024 uint4
            int idx = tid + p * 128;
            int r = idx >> 3, cc = (idx & 7) * 8;
            cpasync16(sA + (uint32_t)(r * WLDA + cc) * 2,
                      &A[(size_t)(mbase + r) * K + k0 + cc]);
        }
#pragma unroll
        for (int p = 0; p < 8; p++) {          // B: 64x128 = 1024 uint4
            int idx = tid + p * 128;
            int r = idx >> 4, cc = (idx & 15) * 8;
            cpasync16(sB + (uint32_t)(r * WLDB + cc) * 2,
                      &W[(size_t)(k0 + r) * N + nbase + cc]);
        }
        asm volatile("cp.async.commit_group;" ::: "memory");
    };

    load_stage(0, 0);
    for (int kc = 0; kc < nch; kc++) {
        if (kc + 1 < nch) load_stage((kc + 1) & 1, (kc + 1) * 64);
        if (kc + 1 < nch)
            asm volatile("cp.async.wait_group 1;" ::: "memory");
        else
            asm volatile("cp.async.wait_group 0;" ::: "memory");
        __syncthreads();

        uint32_t sA = sbase + (uint32_t)((kc & 1) * WSTG) * 2;
        uint32_t sB = sA + (uint32_t)WAST * 2;
#pragma unroll
        for (int kk = 0; kk < 64; kk += 16) {
            uint32_t af[4][4], bfr[4][4];
#pragma unroll
            for (int mi = 0; mi < 4; mi++)
                ldsm_x4(af[mi],
                    sA + (uint32_t)((aRow + mi * 16) * WLDA + kk + aKad) * 2);
#pragma unroll
            for (int nh = 0; nh < 4; nh++)
                ldsm_x4t(bfr[nh],
                    sB + (uint32_t)((kk + bKad) * WLDB + bNad + nh * 16) * 2);
#pragma unroll
            for (int mi = 0; mi < 4; mi++)
#pragma unroll
                for (int ni = 0; ni < 8; ni++)
                    mma16816(c[mi][ni], af[mi], &bfr[ni >> 1][(ni & 1) * 2]);
        }
        __syncthreads();
    }

    int grp = lane >> 2;
    int qid = lane & 3;
#pragma unroll
    for (int mi = 0; mi < 4; mi++) {
#pragma unroll
        for (int ni = 0; ni < 8; ni++) {
            int col = nbase + warpN * 64 + ni * 8 + qid * 2;
            float b0 = bias[col], b1 = bias[col + 1];
#pragma unroll
            for (int half = 0; half < 2; half++) {
                int row = mbase + warpM * 64 + mi * 16 + grp + half * 8;
                float v0 = gelu_tanh(c[mi][ni][half * 2 + 0] + b0);
                float v1 = gelu_tanh(c[mi][ni][half * 2 + 1] + b1);
                *(uint32_t*)&Cout[(size_t)row * N + col] = packbf2(v0, v1);
            }
        }
    }
}

// ---------------- tensor-core cluster attention (R8 version) -----------------
#define ACLS 584
#define ASMB (M_CL * ACLS * 2)

__global__ __launch_bounds__(192) void attn_tc(const bf16* __restrict__ qkv,
                                               bf16* __restrict__ o) {
    extern __shared__ __align__(16) bf16 sm[];
    int blk  = blockIdx.x;
    int tid  = threadIdx.x;
    int h    = tid >> 5;
    int lane = tid & 31;

    size_t gbase = (size_t)blk * (M_CL * 3 * D);
#pragma unroll
    for (int p = 0; p < 24; p++) {
        int idx = tid + p * 192;
        int r = idx / 72, cc = (idx % 72) * 8;
        *(uint4*)&sm[r * ACLS + cc] = *(const uint4*)&qkv[gbase + (size_t)r * 576 + cc];
    }
    __syncthreads();

    uint32_t sb    = smem_u32(sm);
    uint32_t qbse  = sb + (uint32_t)(h * 32) * 2;
    uint32_t kbse  = sb + (uint32_t)(D + h * 32) * 2;
    uint32_t vbse  = sb + (uint32_t)(2 * D + h * 32) * 2;

    uint32_t kb[4][2][4];
    int krow = (lane & 7) + ((lane >> 4) & 1) * 8;
    int kcol = ((lane >> 3) & 1) * 8;
#pragma unroll
    for (int jb = 0; jb < 4; jb++)
#pragma unroll
        for (int db = 0; db < 2; db++)
            ldsm_x4(kb[jb][db],
                kbse + (uint32_t)((jb * 16 + krow) * ACLS + db * 16 + kcol) * 2);

    uint32_t vb[4][2][4];
    int vkrow = ((lane >> 3) & 1) * 8 + (lane & 7);
    int vnad  = (lane >> 4) * 8;
#pragma unroll
    for (int jb = 0; jb < 4; jb++)
#pragma unroll
        for (int db = 0; db < 2; db++)
            ldsm_x4t(vb[jb][db],
                vbse + (uint32_t)((jb * 16 + vkrow) * ACLS + db * 16 + vnad) * 2);

    const float scale = 0.17677669529663687f;
    int arow = lane & 15, akad = (lane >> 4) << 3;
    int grp = lane >> 2;

#pragma unroll
    for (int pass = 0; pass < 4; pass++) {
        int qbase = pass * 16;
        uint32_t qa[2][4];
#pragma unroll
        for (int kg = 0; kg < 2; kg++)
            ldsm_x4(qa[kg],
                qbse + (uint32_t)((qbase + arow) * ACLS + kg * 16 + akad) * 2);

        float sacc[8][4];
#pragma unroll
        for (int nt = 0; nt < 8; nt++)
#pragma unroll
            for (int e = 0; e < 4; e++) sacc[nt][e] = 0.f;
#pragma unroll
        for (int kg = 0; kg < 2; kg++)
#pragma unroll
            for (int nt = 0; nt < 8; nt++)
                mma16816(sacc[nt], qa[kg], &kb[nt >> 1][kg][(nt & 1) * 2]);

        float slo = 0.f, shi = 0.f;
#pragma unroll
        for (int nt = 0; nt < 8; nt++) {
            float e0 = __expf(sacc[nt][0] * scale);
            float e1 = __expf(sacc[nt][1] * scale);
            float e2 = __expf(sacc[nt][2] * scale);
            float e3 = __expf(sacc[nt][3] * scale);
            sacc[nt][0] = e0; sacc[nt][1] = e1;
            sacc[nt][2] = e2; sacc[nt][3] = e3;
            slo += e0 + e1; shi += e2 + e3;
        }
        slo += __shfl_xor_sync(0xffffffffu, slo, 1);
        slo += __shfl_xor_sync(0xffffffffu, slo, 2);
        shi += __shfl_xor_sync(0xffffffffu, shi, 1);
        shi += __shfl_xor_sync(0xffffffffu, shi, 2);

        uint32_t pa[4][4];
#pragma unroll
        for (int jb = 0; jb < 4; jb++) {
            pa[jb][0] = packbf2(sacc[2 * jb][0],     sacc[2 * jb][1]);
            pa[jb][1] = packbf2(sacc[2 * jb][2],     sacc[2 * jb][3]);
            pa[jb][2] = packbf2(sacc[2 * jb + 1][0], sacc[2 * jb + 1][1]);
            pa[jb][3] = packbf2(sacc[2 * jb + 1][2], sacc[2 * jb + 1][3]);
        }

        float oacc[4][4];
#pragma unroll
        for (int nt = 0; nt < 4; nt++)
#pragma unroll
            for (int e = 0; e < 4; e++) oacc[nt][e] = 0.f;
#pragma unroll
        for (int kg = 0; kg < 4; kg++)
#pragma unroll
            for (int nt = 0; nt < 4; nt++)
                mma16816(oacc[nt], pa[kg], &vb[kg][nt >> 1][(nt & 1) * 2]);

        float inv0 = 1.f / slo, inv1 = 1.f / shi;
        int r0 = qbase + grp;
        int tok0 = g_ord[blk * M_CL + r0];
        int tok1 = g_ord[blk * M_CL + r0 + 8];
#pragma unroll
        for (int nt = 0; nt < 4; nt++) {
            int col = h * 32 + nt * 8 + (lane & 3) * 2;
            *(uint32_t*)&o[(size_t)tok0 * D + col] =
                packbf2(oacc[nt][0] * inv0, oacc[nt][1] * inv0);
            *(uint32_t*)&o[(size_t)tok1 * D + col] =
                packbf2(oacc[nt][2] * inv1, oacc[nt][3] * inv1);
        }
    }
}

// ---------------- launch ------------------------------------------------------
extern "C" void kernel_launch(void* const* d_in, const int* in_sizes, int n_in,
                              void* d_out, int out_size) {
    const float* x      = (const float*)d_in[0];
    const float* pos    = (const float*)d_in[1];
    const float* ln1_g  = (const float*)d_in[2];
    const float* ln1_b  = (const float*)d_in[3];
    const float* w_qkv  = (const float*)d_in[4];
    const float* b_qkv  = (const float*)d_in[5];
    const float* w_proj = (const float*)d_in[6];
    const float* b_proj = (const float*)d_in[7];
    const float* ln2_g  = (const float*)d_in[8];
    const float* ln2_b  = (const float*)d_in[9];
    const float* w_fc1  = (const float*)d_in[10];
    const float* b_fc1  = (const float*)d_in[11];
    const float* w_fc2  = (const float*)d_in[12];
    const float* b_fc2  = (const float*)d_in[13];
    float* out = (float*)d_out;

    bf16 *xn, *qkv, *o, *hbuf, *wqkv, *wprj, *wfc1, *wfc2;
    int *inv;
    cudaGetSymbolAddress((void**)&xn,   g_xn);
    cudaGetSymbolAddress((void**)&qkv,  g_qkv);
    cudaGetSymbolAddress((void**)&o,    g_o);
    cudaGetSymbolAddress((void**)&hbuf, g_h);
    cudaGetSymbolAddress((void**)&wqkv, g_wqkv);
    cudaGetSymbolAddress((void**)&wprj, g_wprj);
    cudaGetSymbolAddress((void**)&wfc1, g_wfc1);
    cudaGetSymbolAddress((void**)&wfc2, g_wfc2);
    cudaGetSymbolAddress((void**)&inv,  g_inv);

    cudaFuncSetAttribute(gemm_mma<0, true,  false, true >,
        cudaFuncAttributeMaxDynamicSharedMemorySize, SMEMB);
    cudaFuncSetAttribute(gemm_mma<0, false, true,  false>,
        cudaFuncAttributeMaxDynamicSharedMemorySize, SMEMB);
    cudaFuncSetAttribute(gemm_w128,
        cudaFuncAttributeMaxDynamicSharedMemorySize, SMEMW);
    cudaFuncSetAttribute(attn_tc,
        cudaFuncAttributeMaxDynamicSharedMemorySize, ASMB);

    prep_kernel<<<(SZ_FC1 + 255) / 256, 256>>>(w_qkv, w_proj, w_fc1, w_fc2, pos); // 1

    dim3 gQKV(3 * D / BNm, BN_ROWS / BMm);   // (9, 512)
    dim3 gPRJ(D / BNm,     BN_ROWS / BMm);   // (3, 512)
    dim3 gFC1(DFF / 128,   BN_ROWS / 128);   // (6, 512)
    dim3 gFC2(D / BNm,     BN_ROWS / BMm);   // (3, 512)
    int lnBlocks = BN_ROWS / 8;

    for (int i = 0; i < 2; i++) {
        const float* xin = (i == 0) ? x : out;
        ln_kernel<<<lnBlocks, 256>>>(xin, ln1_g + i * D, ln1_b + i * D, xn);  // 2
        gemm_mma<0, true, false, true><<<gQKV, 128, SMEMB>>>(                 // 3
            xn, wqkv + (size_t)i * D * 3 * D, b_qkv + i * 3 * D,
            nullptr, inv, qkv, D, 3 * D);
        attn_tc<<<BATCH * KC, 192, ASMB>>>(qkv, o);                           // 4
        gemm_mma<0, false, true, false><<<gPRJ, 128, SMEMB>>>(                // 5 <- capture
            o, wprj + (size_t)i * D * D, b_proj + i * D,
            xin, nullptr, out, D, D);
        ln_kernel<<<lnBlocks, 256>>>(out, ln2_g + i * D, ln2_b + i * D, xn);
        gemm_w128<<<gFC1, 128, SMEMW>>>(
            xn, wfc1 + (size_t)i * D * DFF, b_fc1 + i * DFF, hbuf, D, DFF);
        gemm_mma<0, false, true, false><<<gFC2, 128, SMEMB>>>(
            hbuf, wfc2 + (size_t)i * DFF * D, b_fc2 + i * D,
            out, nullptr, out, DFF, D);
    }
}

// round 17
// speedup vs baseline: 1.0958x; 1.0958x over previous
#include <cuda_runtime.h>
#include <cuda_bf16.h>
#include <cstdint>
#include <math.h>

#define BATCH    4
#define N_TOK    16384
#define D        192
#define DFF      768
#define HEADS    6
#define DH       32
#define M_CL     64
#define KC       (N_TOK / M_CL)
#define BN_ROWS  (BATCH * N_TOK)     // 65536
#define GRID_W   128

typedef __nv_bfloat16 bf16;

// ---------------- scratch ----------------------------------------------------
__device__ bf16  g_xn  [BN_ROWS * D];
__device__ bf16  g_qkv [BN_ROWS * 3 * D];
__device__ bf16  g_o   [BN_ROWS * D];
__device__ bf16  g_h   [BN_ROWS * DFF];
__device__ bf16  g_wqkv[2 * D * 3 * D];     // [K][N] bf16
__device__ bf16  g_wprj[2 * D * D];
__device__ bf16  g_wfc1[2 * D * DFF];
__device__ bf16  g_wfc2[2 * DFF * D];
__device__ int   g_ord[BN_ROWS];
__device__ int   g_inv[BN_ROWS];

// ---------------- helpers ----------------------------------------------------
__device__ __forceinline__ uint32_t smem_u32(const void* p) {
    uint32_t a;
    asm("{ .reg .u64 t; cvta.to.shared.u64 t, %1; cvt.u32.u64 %0, t; }"
        : "=r"(a) : "l"(p));
    return a;
}
__device__ __forceinline__ void cpasync16(uint32_t saddr, const void* g) {
    asm volatile("cp.async.cg.shared.global [%0], [%1], 16;"
                 :: "r"(saddr), "l"(g) : "memory");
}
__device__ __forceinline__ void ldsm_x4(uint32_t* r, uint32_t addr) {
    asm volatile("ldmatrix.sync.aligned.m8n8.x4.shared.b16 {%0,%1,%2,%3}, [%4];"
                 : "=r"(r[0]), "=r"(r[1]), "=r"(r[2]), "=r"(r[3]) : "r"(addr));
}
__device__ __forceinline__ void ldsm_x4t(uint32_t* r, uint32_t addr) {
    asm volatile("ldmatrix.sync.aligned.m8n8.x4.trans.shared.b16 {%0,%1,%2,%3}, [%4];"
                 : "=r"(r[0]), "=r"(r[1]), "=r"(r[2]), "=r"(r[3]) : "r"(addr));
}
__device__ __forceinline__ void mma16816(float* c, const uint32_t* a,
                                         const uint32_t* b) {
    asm volatile(
        "mma.sync.aligned.m16n8k16.row.col.f32.bf16.bf16.f32 "
        "{%0,%1,%2,%3}, {%4,%5,%6,%7}, {%8,%9}, {%0,%1,%2,%3};"
        : "+f"(c[0]), "+f"(c[1]), "+f"(c[2]), "+f"(c[3])
        : "r"(a[0]), "r"(a[1]), "r"(a[2]), "r"(a[3]), "r"(b[0]), "r"(b[1]));
}
__device__ __forceinline__ uint32_t packbf2(float lo, float hi) {
    __nv_bfloat162 pk;
    pk.x = __float2bfloat16(lo);
    pk.y = __float2bfloat16(hi);
    return *(uint32_t*)&pk;
}
__device__ __forceinline__ float tanh_hw(float x) {
    float y;
    asm("tanh.approx.f32 %0, %1;" : "=f"(y) : "f"(x));
    return y;
}
__device__ __forceinline__ float gelu_tanh(float v) {
    float c = v + 0.044715f * v * v * v;
    return 0.5f * v * (1.f + tanh_hw(0.7978845608028654f * c));
}

// ---------------- fused prep: weights->bf16 + curve order -------------------
#define SZ_QKV (2 * D * 3 * D)
#define SZ_PRJ (2 * D * D)
#define SZ_FC1 (2 * D * DFF)
#define SZ_FC2 (2 * DFF * D)
__global__ void prep_kernel(const float* __restrict__ wq, const float* __restrict__ wp,
                            const float* __restrict__ w1, const float* __restrict__ w2,
                            const float* __restrict__ pos) {
    int i = blockIdx.x * blockDim.x + threadIdx.x;
    if (i < SZ_QKV) g_wqkv[i] = __float2bfloat16(wq[i]);
    if (i < SZ_PRJ) g_wprj[i] = __float2bfloat16(wp[i]);
    if (i < SZ_FC1) g_wfc1[i] = __float2bfloat16(w1[i]);
    if (i < SZ_FC2) g_wfc2[i] = __float2bfloat16(w2[i]);
    if (i < BN_ROWS) {
        int b = i / N_TOK;
        int ix = (int)floorf(pos[(size_t)i * 2 + 0]);
        int iy = (int)floorf(pos[(size_t)i * 2 + 1]);
        int key = iy * GRID_W + ((iy & 1) ? (GRID_W - 1 - ix) : ix);
        int rank = b * N_TOK + key;
        g_inv[i]    = rank;
        g_ord[rank] = i;
    }
}

// ---------------- layernorm --------------------------------------------------
__global__ void ln_kernel(const float* __restrict__ x,
                          const float* __restrict__ gamma,
                          const float* __restrict__ beta,
                          bf16* __restrict__ out) {
    int warp = (blockIdx.x * blockDim.x + threadIdx.x) >> 5;
    int lane = threadIdx.x & 31;
    if (warp >= BN_ROWS) return;
    const float* xr = x + (size_t)warp * D;
    float v[6];
    float s = 0.f, s2 = 0.f;
#pragma unroll
    for (int j = 0; j < 6; j++) {
        v[j] = xr[lane + 32 * j];
        s += v[j]; s2 += v[j] * v[j];
    }
#pragma unroll
    for (int o = 16; o; o >>= 1) {
        s  += __shfl_xor_sync(0xffffffffu, s,  o);
        s2 += __shfl_xor_sync(0xffffffffu, s2, o);
    }
    float mean = s * (1.f / D);
    float var  = s2 * (1.f / D) - mean * mean;
    float rstd = rsqrtf(var + 1e-5f);
    bf16* orow = out + (size_t)warp * D;
#pragma unroll
    for (int j = 0; j < 6; j++) {
        int c = lane + 32 * j;
        orow[c] = __float2bfloat16((v[j] - mean) * rstd * gamma[c] + beta[c]);
    }
}

// ---------------- raw mma.sync GEMM (all four GEMMs) -------------------------
#define BMm   128
#define BNm   64
#define BKm   64
#define LDAS  72
#define LDBS  72
#define AST   (BMm * LDAS)
#define BST   (BKm * LDBS)
#define STAGE (AST + BST)
#define SMEMB (2 * STAGE * 2)

template <int ACT, bool SCATTER, bool RES, bool OUTBF>
__global__ __launch_bounds__(128) void gemm_mma(
        const bf16*  __restrict__ A,
        const bf16*  __restrict__ W,
        const float* __restrict__ bias,
        const float* __restrict__ res,
        const int*   __restrict__ omap,
        void* __restrict__ Cout,
        int K, int N) {
    extern __shared__ __align__(16) bf16 sm[];
    uint32_t sbase = smem_u32(sm);

    int tid   = threadIdx.x;
    int wid   = tid >> 5;
    int lane  = tid & 31;
    int warpM = wid >> 1;
    int warpN = wid & 1;
    int mbase = blockIdx.y * BMm;
    int nbase = blockIdx.x * BNm;

    float c[4][4][4];
#pragma unroll
    for (int mi = 0; mi < 4; mi++)
#pragma unroll
        for (int ni = 0; ni < 4; ni++)
#pragma unroll
            for (int e = 0; e < 4; e++) c[mi][ni][e] = 0.f;

    int aRow  = warpM * 64 + (lane & 15);
    int aKad  = (lane >> 4) << 3;
    int bKad  = ((lane >> 3) & 1) * 8 + (lane & 7);
    int bNad  = warpN * 32 + ((lane >> 4) << 3);

    const int nch = K / BKm;

    auto load_stage = [&](int st, int k0) {
        uint32_t sA = sbase + (uint32_t)(st * STAGE) * 2;
        uint32_t sB = sA + (uint32_t)AST * 2;
#pragma unroll
        for (int p = 0; p < 8; p++) {
            int idx = tid + p * 128;
            int r = idx >> 3, cc = (idx & 7) * 8;
            cpasync16(sA + (uint32_t)(r * LDAS + cc) * 2,
                      &A[(size_t)(mbase + r) * K + k0 + cc]);
        }
#pragma unroll
        for (int p = 0; p < 4; p++) {
            int idx = tid + p * 128;
            int r = idx >> 3, cc = (idx & 7) * 8;
            cpasync16(sB + (uint32_t)(r * LDBS + cc) * 2,
                      &W[(size_t)(k0 + r) * N + nbase + cc]);
        }
        asm volatile("cp.async.commit_group;" ::: "memory");
    };

    load_stage(0, 0);
    for (int kc = 0; kc < nch; kc++) {
        if (kc + 1 < nch) load_stage((kc + 1) & 1, (kc + 1) * BKm);
        if (kc + 1 < nch)
            asm volatile("cp.async.wait_group 1;" ::: "memory");
        else
            asm volatile("cp.async.wait_group 0;" ::: "memory");
        __syncthreads();

        uint32_t sA = sbase + (uint32_t)((kc & 1) * STAGE) * 2;
        uint32_t sB = sA + (uint32_t)AST * 2;
#pragma unroll
        for (int kk = 0; kk < BKm; kk += 16) {
            uint32_t af[4][4], bfr[2][4];
#pragma unroll
            for (int mi = 0; mi < 4; mi++)
                ldsm_x4(af[mi],
                    sA + (uint32_t)((aRow + mi * 16) * LDAS + kk + aKad) * 2);
#pragma unroll
            for (int nh = 0; nh < 2; nh++)
                ldsm_x4t(bfr[nh],
                    sB + (uint32_t)((kk + bKad) * LDBS + bNad + nh * 16) * 2);
#pragma unroll
            for (int mi = 0; mi < 4; mi++)
#pragma unroll
                for (int ni = 0; ni < 4; ni++)
                    mma16816(c[mi][ni], af[mi], &bfr[ni >> 1][(ni & 1) * 2]);
        }
        __syncthreads();
    }

    int grp = lane >> 2;
    int qid = lane & 3;
#pragma unroll
    for (int mi = 0; mi < 4; mi++) {
#pragma unroll
        for (int ni = 0; ni < 4; ni++) {
            int col = nbase + warpN * 32 + ni * 8 + qid * 2;
            float b0 = bias[col], b1 = bias[col + 1];
#pragma unroll
            for (int half = 0; half < 2; half++) {
                int row = mbase + warpM * 64 + mi * 16 + grp + half * 8;
                int orow = SCATTER ? omap[row] : row;
                float v0 = c[mi][ni][half * 2 + 0] + b0;
                float v1 = c[mi][ni][half * 2 + 1] + b1;
                if (ACT == 1) { v0 = gelu_tanh(v0); v1 = gelu_tanh(v1); }
                if (RES) {
                    const float2 r2 = *(const float2*)&res[(size_t)orow * N + col];
                    v0 += r2.x; v1 += r2.y;
                }
                if (OUTBF) {
                    *(uint32_t*)&((bf16*)Cout)[(size_t)orow * N + col] = packbf2(v0, v1);
                } else {
                    float2 o2; o2.x = v0; o2.y = v1;
                    *(float2*)&((float*)Cout)[(size_t)orow * N + col] = o2;
                }
            }
        }
    }
}

// ---------------- tensor-core cluster attention (R8 version) -----------------
#define ACLS 584
#define ASMB (M_CL * ACLS * 2)

__global__ __launch_bounds__(192) void attn_tc(const bf16* __restrict__ qkv,
                                               bf16* __restrict__ o) {
    extern __shared__ __align__(16) bf16 sm[];
    int blk  = blockIdx.x;
    int tid  = threadIdx.x;
    int h    = tid >> 5;
    int lane = tid & 31;

    size_t gbase = (size_t)blk * (M_CL * 3 * D);
#pragma unroll
    for (int p = 0; p < 24; p++) {
        int idx = tid + p * 192;
        int r = idx / 72, cc = (idx % 72) * 8;
        *(uint4*)&sm[r * ACLS + cc] = *(const uint4*)&qkv[gbase + (size_t)r * 576 + cc];
    }
    __syncthreads();

    uint32_t sb    = smem_u32(sm);
    uint32_t qbse  = sb + (uint32_t)(h * 32) * 2;
    uint32_t kbse  = sb + (uint32_t)(D + h * 32) * 2;
    uint32_t vbse  = sb + (uint32_t)(2 * D + h * 32) * 2;

    uint32_t kb[4][2][4];
    int krow = (lane & 7) + ((lane >> 4) & 1) * 8;
    int kcol = ((lane >> 3) & 1) * 8;
#pragma unroll
    for (int jb = 0; jb < 4; jb++)
#pragma unroll
        for (int db = 0; db < 2; db++)
            ldsm_x4(kb[jb][db],
                kbse + (uint32_t)((jb * 16 + krow) * ACLS + db * 16 + kcol) * 2);

    uint32_t vb[4][2][4];
    int vkrow = ((lane >> 3) & 1) * 8 + (lane & 7);
    int vnad  = (lane >> 4) * 8;
#pragma unroll
    for (int jb = 0; jb < 4; jb++)
#pragma unroll
        for (int db = 0; db < 2; db++)
            ldsm_x4t(vb[jb][db],
                vbse + (uint32_t)((jb * 16 + vkrow) * ACLS + db * 16 + vnad) * 2);

    const float scale = 0.17677669529663687f;
    int arow = lane & 15, akad = (lane >> 4) << 3;
    int grp = lane >> 2;

#pragma unroll
    for (int pass = 0; pass < 4; pass++) {
        int qbase = pass * 16;
        uint32_t qa[2][4];
#pragma unroll
        for (int kg = 0; kg < 2; kg++)
            ldsm_x4(qa[kg],
                qbse + (uint32_t)((qbase + arow) * ACLS + kg * 16 + akad) * 2);

        float sacc[8][4];
#pragma unroll
        for (int nt = 0; nt < 8; nt++)
#pragma unroll
            for (int e = 0; e < 4; e++) sacc[nt][e] = 0.f;
#pragma unroll
        for (int kg = 0; kg < 2; kg++)
#pragma unroll
            for (int nt = 0; nt < 8; nt++)
                mma16816(sacc[nt], qa[kg], &kb[nt >> 1][kg][(nt & 1) * 2]);

        float slo = 0.f, shi = 0.f;
#pragma unroll
        for (int nt = 0; nt < 8; nt++) {
            float e0 = __expf(sacc[nt][0] * scale);
            float e1 = __expf(sacc[nt][1] * scale);
            float e2 = __expf(sacc[nt][2] * scale);
            float e3 = __expf(sacc[nt][3] * scale);
            sacc[nt][0] = e0; sacc[nt][1] = e1;
            sacc[nt][2] = e2; sacc[nt][3] = e3;
            slo += e0 + e1; shi += e2 + e3;
        }
        slo += __shfl_xor_sync(0xffffffffu, slo, 1);
        slo += __shfl_xor_sync(0xffffffffu, slo, 2);
        shi += __shfl_xor_sync(0xffffffffu, shi, 1);
        shi += __shfl_xor_sync(0xffffffffu, shi, 2);

        uint32_t pa[4][4];
#pragma unroll
        for (int jb = 0; jb < 4; jb++) {
            pa[jb][0] = packbf2(sacc[2 * jb][0],     sacc[2 * jb][1]);
            pa[jb][1] = packbf2(sacc[2 * jb][2],     sacc[2 * jb][3]);
            pa[jb][2] = packbf2(sacc[2 * jb + 1][0], sacc[2 * jb + 1][1]);
            pa[jb][3] = packbf2(sacc[2 * jb + 1][2], sacc[2 * jb + 1][3]);
        }

        float oacc[4][4];
#pragma unroll
        for (int nt = 0; nt < 4; nt++)
#pragma unroll
            for (int e = 0; e < 4; e++) oacc[nt][e] = 0.f;
#pragma unroll
        for (int kg = 0; kg < 4; kg++)
#pragma unroll
            for (int nt = 0; nt < 4; nt++)
                mma16816(oacc[nt], pa[kg], &vb[kg][nt >> 1][(nt & 1) * 2]);

        float inv0 = 1.f / slo, inv1 = 1.f / shi;
        int r0 = qbase + grp;
        int tok0 = g_ord[blk * M_CL + r0];
        int tok1 = g_ord[blk * M_CL + r0 + 8];
#pragma unroll
        for (int nt = 0; nt < 4; nt++) {
            int col = h * 32 + nt * 8 + (lane & 3) * 2;
            *(uint32_t*)&o[(size_t)tok0 * D + col] =
                packbf2(oacc[nt][0] * inv0, oacc[nt][1] * inv0);
            *(uint32_t*)&o[(size_t)tok1 * D + col] =
                packbf2(oacc[nt][2] * inv1, oacc[nt][3] * inv1);
        }
    }
}

// ---------------- launch ------------------------------------------------------
extern "C" void kernel_launch(void* const* d_in, const int* in_sizes, int n_in,
                              void* d_out, int out_size) {
    const float* x      = (const float*)d_in[0];
    const float* pos    = (const float*)d_in[1];
    const float* ln1_g  = (const float*)d_in[2];
    const float* ln1_b  = (const float*)d_in[3];
    const float* w_qkv  = (const float*)d_in[4];
    const float* b_qkv  = (const float*)d_in[5];
    const float* w_proj = (const float*)d_in[6];
    const float* b_proj = (const float*)d_in[7];
    const float* ln2_g  = (const float*)d_in[8];
    const float* ln2_b  = (const float*)d_in[9];
    const float* w_fc1  = (const float*)d_in[10];
    const float* b_fc1  = (const float*)d_in[11];
    const float* w_fc2  = (const float*)d_in[12];
    const float* b_fc2  = (const float*)d_in[13];
    float* out = (float*)d_out;

    bf16 *xn, *qkv, *o, *hbuf, *wqkv, *wprj, *wfc1, *wfc2;
    int *inv;
    cudaGetSymbolAddress((void**)&xn,   g_xn);
    cudaGetSymbolAddress((void**)&qkv,  g_qkv);
    cudaGetSymbolAddress((void**)&o,    g_o);
    cudaGetSymbolAddress((void**)&hbuf, g_h);
    cudaGetSymbolAddress((void**)&wqkv, g_wqkv);
    cudaGetSymbolAddress((void**)&wprj, g_wprj);
    cudaGetSymbolAddress((void**)&wfc1, g_wfc1);
    cudaGetSymbolAddress((void**)&wfc2, g_wfc2);
    cudaGetSymbolAddress((void**)&inv,  g_inv);

    cudaFuncSetAttribute(gemm_mma<0, true,  false, true >,
        cudaFuncAttributeMaxDynamicSharedMemorySize, SMEMB);
    cudaFuncSetAttribute(gemm_mma<0, false, true,  false>,
        cudaFuncAttributeMaxDynamicSharedMemorySize, SMEMB);
    cudaFuncSetAttribute(gemm_mma<1, false, false, true >,
        cudaFuncAttributeMaxDynamicSharedMemorySize, SMEMB);
    cudaFuncSetAttribute(attn_tc,
        cudaFuncAttributeMaxDynamicSharedMemorySize, ASMB);

    prep_kernel<<<(SZ_FC1 + 255) / 256, 256>>>(w_qkv, w_proj, w_fc1, w_fc2, pos); // 1

    dim3 gQKV(3 * D / BNm, BN_ROWS / BMm);   // (9, 512)
    dim3 gPRJ(D / BNm,     BN_ROWS / BMm);   // (3, 512)
    dim3 gFC1(DFF / BNm,   BN_ROWS / BMm);   // (12, 512)
    dim3 gFC2(D / BNm,     BN_ROWS / BMm);   // (3, 512)
    int lnBlocks = BN_ROWS / 8;

    for (int i = 0; i < 2; i++) {
        const float* xin = (i == 0) ? x : out;
        ln_kernel<<<lnBlocks, 256>>>(xin, ln1_g + i * D, ln1_b + i * D, xn);  // 2
        gemm_mma<0, true, false, true><<<gQKV, 128, SMEMB>>>(                 // 3
            xn, wqkv + (size_t)i * D * 3 * D, b_qkv + i * 3 * D,
            nullptr, inv, qkv, D, 3 * D);
        attn_tc<<<BATCH * KC, 192, ASMB>>>(qkv, o);                           // 4
        gemm_mma<0, false, true, false><<<gPRJ, 128, SMEMB>>>(                // 5
            o, wprj + (size_t)i * D * D, b_proj + i * D,
            xin, nullptr, out, D, D);
        ln_kernel<<<lnBlocks, 256>>>(out, ln2_g + i * D, ln2_b + i * D, xn);  // 6
        gemm_mma<1, false, false, true><<<gFC1, 128, SMEMB>>>(
            xn, wfc1 + (size_t)i * D * DFF, b_fc1 + i * DFF,
            nullptr, nullptr, hbuf, D, DFF);
        gemm_mma<0, false, true, false><<<gFC2, 128, SMEMB>>>(
            hbuf, wfc2 + (size_t)i * DFF * D, b_fc2 + i * D,
            out, nullptr, out, DFF, D);
    }
}